// round 5
// baseline (speedup 1.0000x reference)
#include <cuda_runtime.h>
#include <math.h>
#include <stdint.h>

// ---------------- static problem config ----------------
#define TOKENS   100352      // 32 * 56 * 56  == 2048 windows * 49
#define CDIM     256
#define SDIM     49
#define IMG      56
#define WIN      7
#define SHIFT    3
#define NMLP     1024
#define NWINTOT  16384
#define SCALE    0.17677669529663687f

// ---------------- device scratch ----------------
__device__ float g_xw  [TOKENS * CDIM];          // K-permuted
__device__ float g_qkv [TOKENS * 3 * CDIM];      // natural
__device__ float g_attn[TOKENS * CDIM];          // K-permuted
__device__ float g_x1  [TOKENS * CDIM];          // natural
__device__ float g_xn2 [TOKENS * CDIM];          // K-permuted
__device__ float g_h   [TOKENS * NMLP];          // K-permuted
__device__ float g_wT  [768*256 + 256*256 + 1024*256 + 256*1024];  // K-permuted

#define WT_QKV  0
#define WT_PROJ (768*256)
#define WT_W1   (768*256 + 256*256)
#define WT_W2   (768*256 + 256*256 + 1024*256)

// permuted position of column c within its 8-group: [k0,k4,k1,k5,k2,k6,k3,k7]
__device__ __forceinline__ int ppos(int c) {
    return (c & ~7) | ((c & 3) << 1) | ((c >> 2) & 1);
}

// ---------------- helpers ----------------
__device__ __forceinline__ uint32_t smem_u32(const void* p) {
    uint32_t a;
    asm("{ .reg .u64 t; cvta.to.shared.u64 t, %1; cvt.u32.u64 %0, t; }" : "=r"(a) : "l"(p));
    return a;
}
__device__ __forceinline__ float tf32r(float x) {
    uint32_t u; asm("cvt.rna.tf32.f32 %0, %1;" : "=r"(u) : "f"(x));
    return __uint_as_float(u);
}
__device__ __forceinline__ void cp_async16(uint32_t dst, const void* src) {
    asm volatile("cp.async.cg.shared.global [%0], [%1], 16;" :: "r"(dst), "l"(src));
}
__device__ __forceinline__ void mma_tf32(float* c, const uint32_t* a, const uint32_t* b) {
    asm volatile(
        "mma.sync.aligned.m16n8k8.row.col.f32.tf32.tf32.f32 "
        "{%0,%1,%2,%3}, {%4,%5,%6,%7}, {%8,%9}, {%0,%1,%2,%3};"
        : "+f"(c[0]), "+f"(c[1]), "+f"(c[2]), "+f"(c[3])
        : "r"(a[0]), "r"(a[1]), "r"(a[2]), "r"(a[3]), "r"(b[0]), "r"(b[1]));
}

// window-order row -> token-order row
__device__ __forceinline__ int rowmap(int r) {
    int bw = r / 49;
    int s  = r - bw * 49;
    int b    = bw >> 6;
    int widx = bw & 63;
    int sy = s / 7, sx = s - sy * 7;
    int sh_h = ((widx >> 3) * 7) + sy;
    int sh_w = ((widx & 7) * 7) + sx;
    int oh = sh_h + SHIFT; if (oh >= IMG) oh -= IMG;
    int ow = sh_w + SHIFT; if (ow >= IMG) ow -= IMG;
    return b * (IMG * IMG) + oh * IMG + ow;
}

// ---------------- weight transpose: in[K][N] -> out[N][perm(K)], tf32-rounded ----------------
__global__ void transpose_k(const float* __restrict__ in, float* __restrict__ out,
                            int K, int N)
{
    __shared__ float t[32][33];
    int n0 = blockIdx.x << 5, k0 = blockIdx.y << 5;
    int x = threadIdx.x, y = threadIdx.y;          // 32 x 8
#pragma unroll
    for (int dy = 0; dy < 32; dy += 8)
        t[y + dy][x] = in[(size_t)(k0 + y + dy) * N + n0 + x];
    __syncthreads();
    int px = (x & ~7) | ((x & 3) << 1) | ((x >> 2) & 1);
#pragma unroll
    for (int dy = 0; dy < 32; dy += 8)
        out[(size_t)(n0 + y + dy) * K + k0 + px] = tf32r(t[x][y + dy]);
}

// ---------------- LayerNorm (warp per token), K-permuted tf32 output ----------------
template<bool GATHER>
__global__ void ln_kernel(const float* __restrict__ x,
                          const float* __restrict__ gamma,
                          const float* __restrict__ beta,
                          float* __restrict__ out)
{
    int gw   = (blockIdx.x * blockDim.x + threadIdx.x) >> 5;
    int lane = threadIdx.x & 31;
    if (gw >= TOKENS) return;

    int src = GATHER ? rowmap(gw) : gw;
    const float4* xr = (const float4*)(x + (size_t)src * CDIM);
    float4 v0 = xr[lane];
    float4 v1 = xr[lane + 32];

    float sum = v0.x + v0.y + v0.z + v0.w + v1.x + v1.y + v1.z + v1.w;
    float sq  = v0.x*v0.x + v0.y*v0.y + v0.z*v0.z + v0.w*v0.w
              + v1.x*v1.x + v1.y*v1.y + v1.z*v1.z + v1.w*v1.w;
#pragma unroll
    for (int o = 16; o; o >>= 1) {
        sum += __shfl_xor_sync(0xffffffffu, sum, o);
        sq  += __shfl_xor_sync(0xffffffffu, sq,  o);
    }
    float mu   = sum * (1.0f / 256.0f);
    float var  = sq * (1.0f / 256.0f) - mu * mu;
    float rstd = rsqrtf(var + 1e-5f);

    float4 g0 = ((const float4*)gamma)[lane];
    float4 g1 = ((const float4*)gamma)[lane + 32];
    float4 b0 = ((const float4*)beta )[lane];
    float4 b1 = ((const float4*)beta )[lane + 32];

    float o0[4], o1[4];
    o0[0] = tf32r((v0.x - mu) * rstd * g0.x + b0.x);
    o0[1] = tf32r((v0.y - mu) * rstd * g0.y + b0.y);
    o0[2] = tf32r((v0.z - mu) * rstd * g0.z + b0.z);
    o0[3] = tf32r((v0.w - mu) * rstd * g0.w + b0.w);
    o1[0] = tf32r((v1.x - mu) * rstd * g1.x + b1.x);
    o1[1] = tf32r((v1.y - mu) * rstd * g1.y + b1.y);
    o1[2] = tf32r((v1.z - mu) * rstd * g1.z + b1.z);
    o1[3] = tf32r((v1.w - mu) * rstd * g1.w + b1.w);

    float* orow = out + (size_t)gw * CDIM;
#pragma unroll
    for (int i = 0; i < 4; i++) {
        int c0 = 4 * lane + i;
        int c1 = 128 + c0;
        orow[ppos(c0)] = o0[i];
        orow[ppos(c1)] = o1[i];
    }
}

// ---------------- tf32 mma.sync GEMM (operands K-permuted) ----------------
// Block 128x128, 8 warps (2m x 4n), warp tile 64x32, k-chunk 16, 2-stage cp.async.
// Fragment pairs (k=p, k=p+4) are contiguous float2 in smem (stride 24: conflict-free).
// EPI 0: store   EPI 1: GELU -> K-permuted store   EPI 2: scatter+residual   EPI 3: residual
template<int EPI>
__global__ void __launch_bounds__(256)
tc_gemm(const float* __restrict__ A,
        const float* __restrict__ Bt,
        const float* __restrict__ bias,
        float* __restrict__ Cd,
        const float* __restrict__ res,
        int N, int K)
{
    __shared__ float As[2][128][24];
    __shared__ float Bs[2][128][24];

    int tid  = threadIdx.x;
    int lane = tid & 31;
    int wid  = tid >> 5;
    int wm   = wid >> 2;
    int wn   = wid & 3;
    int bm   = blockIdx.y << 7;
    int bn   = blockIdx.x << 7;

    int lrow = tid >> 2;          // 0..63
    int k4   = (tid & 3) << 2;    // 0,4,8,12 (permuted positions copy straight)

    const float* Ag = A  + (size_t)(bm + lrow) * K + k4;
    const float* Bg = Bt + (size_t)(bn + lrow) * K + k4;

    float acc[4][4][4];
#pragma unroll
    for (int mt = 0; mt < 4; mt++)
#pragma unroll
        for (int nt = 0; nt < 4; nt++)
#pragma unroll
            for (int i = 0; i < 4; i++) acc[mt][nt][i] = 0.0f;

    const int nch = K >> 4;

    cp_async16(smem_u32(&As[0][lrow][k4]),      Ag);
    cp_async16(smem_u32(&As[0][lrow + 64][k4]), Ag + (size_t)64 * K);
    cp_async16(smem_u32(&Bs[0][lrow][k4]),      Bg);
    cp_async16(smem_u32(&Bs[0][lrow + 64][k4]), Bg + (size_t)64 * K);
    asm volatile("cp.async.commit_group;" ::: "memory");

    int q = lane >> 2, p = lane & 3;

    for (int c = 0; c < nch; ++c) {
        if (c + 1 < nch) {
            int nb = (c + 1) & 1;
            int k0 = (c + 1) << 4;
            cp_async16(smem_u32(&As[nb][lrow][k4]),      Ag + k0);
            cp_async16(smem_u32(&As[nb][lrow + 64][k4]), Ag + (size_t)64 * K + k0);
            cp_async16(smem_u32(&Bs[nb][lrow][k4]),      Bg + k0);
            cp_async16(smem_u32(&Bs[nb][lrow + 64][k4]), Bg + (size_t)64 * K + k0);
            asm volatile("cp.async.commit_group;" ::: "memory");
            asm volatile("cp.async.wait_group 1;" ::: "memory");
        } else {
            asm volatile("cp.async.wait_group 0;" ::: "memory");
        }
        __syncthreads();

        int buf = c & 1;
#pragma unroll
        for (int g = 0; g < 2; g++) {
            uint32_t afr[4][4], bfr[4][2];
            int ko = g * 8 + 2 * p;
#pragma unroll
            for (int mt = 0; mt < 4; mt++) {
                int r0 = wm * 64 + mt * 16 + q;
                float2 alo = *(const float2*)&As[buf][r0    ][ko];
                float2 ahi = *(const float2*)&As[buf][r0 + 8][ko];
                afr[mt][0] = __float_as_uint(alo.x);
                afr[mt][1] = __float_as_uint(ahi.x);
                afr[mt][2] = __float_as_uint(alo.y);
                afr[mt][3] = __float_as_uint(ahi.y);
            }
#pragma unroll
            for (int nt = 0; nt < 4; nt++) {
                int n0 = wn * 32 + nt * 8 + q;
                float2 b2 = *(const float2*)&Bs[buf][n0][ko];
                bfr[nt][0] = __float_as_uint(b2.x);
                bfr[nt][1] = __float_as_uint(b2.y);
            }
#pragma unroll
            for (int mt = 0; mt < 4; mt++)
#pragma unroll
                for (int nt = 0; nt < 4; nt++)
                    mma_tf32(acc[mt][nt], afr[mt], bfr[nt]);
        }
        __syncthreads();
    }

    // ---------------- epilogue ----------------
#pragma unroll
    for (int mt = 0; mt < 4; mt++) {
#pragma unroll
        for (int half = 0; half < 2; half++) {
            int r   = bm + wm * 64 + mt * 16 + q + half * 8;
            int dst = (EPI == 2) ? rowmap(r) : r;
            size_t rowbase = (size_t)dst * N;
#pragma unroll
            for (int nt = 0; nt < 4; nt++) {
                int col = bn + wn * 32 + nt * 8 + p * 2;
                float x0 = acc[mt][nt][half * 2 + 0];
                float x1 = acc[mt][nt][half * 2 + 1];
                float2 bi = *(const float2*)(bias + col);
                x0 += bi.x; x1 += bi.y;
                if (EPI == 1) {
                    x0 = tf32r(0.5f * x0 * (1.0f + erff(x0 * 0.70710678118654752f)));
                    x1 = tf32r(0.5f * x1 * (1.0f + erff(x1 * 0.70710678118654752f)));
                    int cb = bn + wn * 32 + nt * 8;
                    int w0 = 2 * p,     pp0 = ((w0 & 3) << 1) | ((w0 >> 2) & 1);
                    int w1 = 2 * p + 1, pp1 = ((w1 & 3) << 1) | ((w1 >> 2) & 1);
                    Cd[rowbase + cb + pp0] = x0;
                    Cd[rowbase + cb + pp1] = x1;
                } else {
                    if (EPI >= 2) {
                        float2 rr = *(const float2*)(res + rowbase + col);
                        x0 += rr.x; x1 += rr.y;
                    }
                    float2 o; o.x = x0; o.y = x1;
                    *(float2*)(Cd + rowbase + col) = o;
                }
            }
        }
    }
}

// ---------------- windowed attention, register-blocked; K-permuted output ----------------
__global__ void __launch_bounds__(128) attn_kernel(
        const float* __restrict__ qkv,
        const float* __restrict__ bias_table,
        float* __restrict__ out)
{
    int h  = blockIdx.x & 7;
    int bw = blockIdx.x >> 3;
    int widx = bw & 63;

    __shared__ float q[SDIM][36];
    __shared__ float k[SDIM][36];
    __shared__ float v[SDIM][36];
    __shared__ float sc[SDIM][50];
    __shared__ float btab[169];
    __shared__ int   reg[SDIM];

    int tid = threadIdx.x;

    for (int i = tid; i < 169; i += 128) btab[i] = bias_table[i * 8 + h];

    if (tid < SDIM) {
        int sy = tid / 7, sx = tid - sy * 7;
        int sh_h = ((widx >> 3) * 7) + sy;
        int sh_w = ((widx & 7) * 7) + sx;
        int fh = (sh_h < 49) ? 0 : ((sh_h < 53) ? 1 : 2);
        int fw = (sh_w < 49) ? 0 : ((sh_w < 53) ? 1 : 2);
        reg[tid] = (fw == 1) ? 0 : (fh * 3 + fw);
    }

    // load q (scaled), k, v: float4 per unit
    for (int i = tid; i < SDIM * 8; i += 128) {
        int s = i >> 3, d4 = (i & 7) << 2;
        size_t base = (size_t)(bw * 49 + s) * 768 + h * 32 + d4;
        float4 qq = *(const float4*)(qkv + base);
        float4 kk = *(const float4*)(qkv + base + 256);
        float4 vv = *(const float4*)(qkv + base + 512);
        qq.x *= SCALE; qq.y *= SCALE; qq.z *= SCALE; qq.w *= SCALE;
        *(float4*)&q[s][d4] = qq;
        *(float4*)&k[s][d4] = kk;
        *(float4*)&v[s][d4] = vv;
    }
    __syncthreads();

    // score phase: unit = (s, half); q row cached in registers
    if (tid < 98) {
        int s = tid >> 1, half = tid & 1;
        float4 qr[8];
#pragma unroll
        for (int d4 = 0; d4 < 8; d4++) qr[d4] = *(const float4*)&q[s][d4 << 2];
        int sy = s / 7, sx = s - sy * 7;
        int rs = reg[s];
        int t0 = half * 25, t1 = half ? 49 : 25;
        for (int t = t0; t < t1; t++) {
            float a = 0.0f;
#pragma unroll
            for (int d4 = 0; d4 < 8; d4++) {
                float4 kv = *(const float4*)&k[t][d4 << 2];
                a += qr[d4].x * kv.x + qr[d4].y * kv.y
                   + qr[d4].z * kv.z + qr[d4].w * kv.w;
            }
            int ty = t / 7, tx = t - ty * 7;
            a += btab[(sy - ty + 6) * 13 + (sx - tx + 6)];
            if (rs != reg[t]) a -= 100.0f;
            sc[s][t] = a;
        }
    }
    __syncthreads();

    // softmax per row
    if (tid < SDIM) {
        float mx = -1e30f;
#pragma unroll 7
        for (int t = 0; t < 49; t++) mx = fmaxf(mx, sc[tid][t]);
        float sum = 0.0f;
#pragma unroll 7
        for (int t = 0; t < 49; t++) {
            float e = __expf(sc[tid][t] - mx);
            sc[tid][t] = e;
            sum += e;
        }
        float inv = 1.0f / sum;
#pragma unroll 7
        for (int t = 0; t < 49; t++) sc[tid][t] *= inv;
    }
    __syncthreads();

    // AV phase: unit = (s, j): out[s][4j..4j+3]
    for (int u = tid; u < SDIM * 8; u += 128) {
        int s = u >> 3, j = u & 7;
        float a0 = 0, a1 = 0, a2 = 0, a3 = 0;
#pragma unroll 7
        for (int t = 0; t < 49; t++) {
            float w = sc[s][t];
            float4 vv = *(const float4*)&v[t][j << 2];
            a0 += w * vv.x; a1 += w * vv.y; a2 += w * vv.z; a3 += w * vv.w;
        }
        // K-permuted store: natural cols h*32 + 4j + e
        float* orow = out + (size_t)(bw * 49 + s) * 256 + h * 32 + ((j >> 1) << 3) + (j & 1);
        orow[0] = tf32r(a0);
        orow[2] = tf32r(a1);
        orow[4] = tf32r(a2);
        orow[6] = tf32r(a3);
    }
}

// ---------------- launch ----------------
extern "C" void kernel_launch(void* const* d_in, const int* in_sizes, int n_in,
                              void* d_out, int out_size)
{
    const float* x       = (const float*)d_in[0];
    const float* gamma   = (const float*)d_in[1];
    const float* beta    = (const float*)d_in[2];
    const float* qkv_w   = (const float*)d_in[3];
    const float* qkv_b   = (const float*)d_in[4];
    const float* proj_w  = (const float*)d_in[5];
    const float* proj_b  = (const float*)d_in[6];
    const float* relbias = (const float*)d_in[7];
    const float* mlp_w1  = (const float*)d_in[8];
    const float* mlp_b1  = (const float*)d_in[9];
    const float* mlp_w2  = (const float*)d_in[10];
    const float* mlp_b2  = (const float*)d_in[11];
    float* outp = (float*)d_out;

    float *xw, *qkvb, *attnb, *x1, *xn2, *hb, *wT;
    cudaGetSymbolAddress((void**)&xw,    g_xw);
    cudaGetSymbolAddress((void**)&qkvb,  g_qkv);
    cudaGetSymbolAddress((void**)&attnb, g_attn);
    cudaGetSymbolAddress((void**)&x1,    g_x1);
    cudaGetSymbolAddress((void**)&xn2,   g_xn2);
    cudaGetSymbolAddress((void**)&hb,    g_h);
    cudaGetSymbolAddress((void**)&wT,    g_wT);

    const int MT = TOKENS / 128;   // 784

    transpose_k<<<dim3(768/32, 256/32),  dim3(32,8)>>>(qkv_w,  wT + WT_QKV,  256, 768);
    transpose_k<<<dim3(256/32, 256/32),  dim3(32,8)>>>(proj_w, wT + WT_PROJ, 256, 256);
    transpose_k<<<dim3(1024/32, 256/32), dim3(32,8)>>>(mlp_w1, wT + WT_W1,   256, 1024);
    transpose_k<<<dim3(256/32, 1024/32), dim3(32,8)>>>(mlp_w2, wT + WT_W2,   1024, 256);

    ln_kernel<true><<<TOKENS / 8, 256>>>(x, gamma, beta, xw);
    tc_gemm<0><<<dim3(6, MT), 256>>>(xw, wT + WT_QKV, qkv_b, qkvb, nullptr, 768, 256);
    attn_kernel<<<NWINTOT, 128>>>(qkvb, relbias, attnb);
    tc_gemm<2><<<dim3(2, MT), 256>>>(attnb, wT + WT_PROJ, proj_b, x1, x, 256, 256);
    ln_kernel<false><<<TOKENS / 8, 256>>>(x1, gamma, beta, xn2);
    tc_gemm<1><<<dim3(8, MT), 256>>>(xn2, wT + WT_W1, mlp_b1, hb, nullptr, 1024, 256);
    tc_gemm<3><<<dim3(2, MT), 256>>>(hb, wT + WT_W2, mlp_b2, outp, x1, 256, 1024);
}

// round 6
// speedup vs baseline: 1.5567x; 1.5567x over previous
#include <cuda_runtime.h>
#include <math.h>
#include <stdint.h>

// ---------------- static problem config ----------------
#define TOKENS   100352      // 32 * 56 * 56  == 2048 windows * 49
#define CDIM     256
#define SDIM     49
#define IMG      56
#define WIN      7
#define SHIFT    3
#define NMLP     1024
#define NWINTOT  16384
#define SCALE    0.17677669529663687f

// ---------------- device scratch ----------------
__device__ float g_xw  [TOKENS * CDIM];
__device__ float g_qkv [TOKENS * 3 * CDIM];
__device__ float g_attn[TOKENS * CDIM];
__device__ float g_x1  [TOKENS * CDIM];
__device__ float g_xn2 [TOKENS * CDIM];
__device__ float g_h   [TOKENS * NMLP];
__device__ float g_wT  [768*256 + 256*256 + 1024*256 + 256*1024];

#define WT_QKV  0
#define WT_PROJ (768*256)
#define WT_W1   (768*256 + 256*256)
#define WT_W2   (768*256 + 256*256 + 1024*256)

// ---------------- helpers ----------------
__device__ __forceinline__ uint32_t smem_u32(const void* p) {
    uint32_t a;
    asm("{ .reg .u64 t; cvta.to.shared.u64 t, %1; cvt.u32.u64 %0, t; }" : "=r"(a) : "l"(p));
    return a;
}
__device__ __forceinline__ float tf32r(float x) {
    uint32_t u; asm("cvt.rna.tf32.f32 %0, %1;" : "=r"(u) : "f"(x));
    return __uint_as_float(u);
}
__device__ __forceinline__ void cp_async16(uint32_t dst, const void* src) {
    asm volatile("cp.async.cg.shared.global [%0], [%1], 16;" :: "r"(dst), "l"(src));
}
__device__ __forceinline__ void mma_tf32(float* c, const uint32_t* a, const uint32_t* b) {
    asm volatile(
        "mma.sync.aligned.m16n8k8.row.col.f32.tf32.tf32.f32 "
        "{%0,%1,%2,%3}, {%4,%5,%6,%7}, {%8,%9}, {%0,%1,%2,%3};"
        : "+f"(c[0]), "+f"(c[1]), "+f"(c[2]), "+f"(c[3])
        : "r"(a[0]), "r"(a[1]), "r"(a[2]), "r"(a[3]), "r"(b[0]), "r"(b[1]));
}

// window-order row -> token-order row
__device__ __forceinline__ int rowmap(int r) {
    int bw = r / 49;
    int s  = r - bw * 49;
    int b    = bw >> 6;
    int widx = bw & 63;
    int sy = s / 7, sx = s - sy * 7;
    int sh_h = ((widx >> 3) * 7) + sy;
    int sh_w = ((widx & 7) * 7) + sx;
    int oh = sh_h + SHIFT; if (oh >= IMG) oh -= IMG;
    int ow = sh_w + SHIFT; if (ow >= IMG) ow -= IMG;
    return b * (IMG * IMG) + oh * IMG + ow;
}

// ---------------- weight transpose (tf32-rounded): in[K][N] -> out[N][K] ----------------
__global__ void transpose_k(const float* __restrict__ in, float* __restrict__ out,
                            int K, int N)
{
    __shared__ float t[32][33];
    int n0 = blockIdx.x << 5, k0 = blockIdx.y << 5;
    int x = threadIdx.x, y = threadIdx.y;          // 32 x 8
#pragma unroll
    for (int dy = 0; dy < 32; dy += 8)
        t[y + dy][x] = in[(size_t)(k0 + y + dy) * N + n0 + x];
    __syncthreads();
#pragma unroll
    for (int dy = 0; dy < 32; dy += 8)
        out[(size_t)(n0 + y + dy) * K + k0 + x] = tf32r(t[x][y + dy]);
}

// ---------------- LayerNorm (warp per token), tf32-rounded output ----------------
template<bool GATHER>
__global__ void ln_kernel(const float* __restrict__ x,
                          const float* __restrict__ gamma,
                          const float* __restrict__ beta,
                          float* __restrict__ out)
{
    int gw   = (blockIdx.x * blockDim.x + threadIdx.x) >> 5;
    int lane = threadIdx.x & 31;
    if (gw >= TOKENS) return;

    int src = GATHER ? rowmap(gw) : gw;
    const float4* xr = (const float4*)(x + (size_t)src * CDIM);
    float4 v0 = xr[lane];
    float4 v1 = xr[lane + 32];

    float sum = v0.x + v0.y + v0.z + v0.w + v1.x + v1.y + v1.z + v1.w;
    float sq  = v0.x*v0.x + v0.y*v0.y + v0.z*v0.z + v0.w*v0.w
              + v1.x*v1.x + v1.y*v1.y + v1.z*v1.z + v1.w*v1.w;
#pragma unroll
    for (int o = 16; o; o >>= 1) {
        sum += __shfl_xor_sync(0xffffffffu, sum, o);
        sq  += __shfl_xor_sync(0xffffffffu, sq,  o);
    }
    float mu   = sum * (1.0f / 256.0f);
    float var  = sq * (1.0f / 256.0f) - mu * mu;
    float rstd = rsqrtf(var + 1e-5f);

    float4 g0 = ((const float4*)gamma)[lane];
    float4 g1 = ((const float4*)gamma)[lane + 32];
    float4 b0 = ((const float4*)beta )[lane];
    float4 b1 = ((const float4*)beta )[lane + 32];

    float4 o0, o1;
    o0.x = tf32r((v0.x - mu) * rstd * g0.x + b0.x);
    o0.y = tf32r((v0.y - mu) * rstd * g0.y + b0.y);
    o0.z = tf32r((v0.z - mu) * rstd * g0.z + b0.z);
    o0.w = tf32r((v0.w - mu) * rstd * g0.w + b0.w);
    o1.x = tf32r((v1.x - mu) * rstd * g1.x + b1.x);
    o1.y = tf32r((v1.y - mu) * rstd * g1.y + b1.y);
    o1.z = tf32r((v1.z - mu) * rstd * g1.z + b1.z);
    o1.w = tf32r((v1.w - mu) * rstd * g1.w + b1.w);

    float4* orow = (float4*)(out + (size_t)gw * CDIM);
    orow[lane]      = o0;
    orow[lane + 32] = o1;
}

// ---------------- tf32 mma.sync GEMM: C[M,N] = A[M,K] @ Bt[N,K]^T + bias ----------------
// Block 128x128, 8 warps (2m x 4n), warp tile 64x32, k-chunk 16.
// 3-stage cp.async pipeline, ONE __syncthreads per chunk.
// EPI 0: store   EPI 1: exact GELU + tf32 round   EPI 2: scatter+residual   EPI 3: residual
template<int EPI>
__global__ void __launch_bounds__(256)
tc_gemm(const float* __restrict__ A,
        const float* __restrict__ Bt,
        const float* __restrict__ bias,
        float* __restrict__ Cd,
        const float* __restrict__ res,
        int N, int K)
{
    __shared__ float As[3][128][20];
    __shared__ float Bs[3][128][20];

    int tid  = threadIdx.x;
    int lane = tid & 31;
    int wid  = tid >> 5;
    int wm   = wid >> 2;
    int wn   = wid & 3;
    int bm   = blockIdx.y << 7;
    int bn   = blockIdx.x << 7;

    int lrow = tid >> 2;          // 0..63
    int k4   = (tid & 3) << 2;    // 0,4,8,12

    const float* Ag = A  + (size_t)(bm + lrow) * K + k4;
    const float* Bg = Bt + (size_t)(bn + lrow) * K + k4;

    float acc[4][4][4];
#pragma unroll
    for (int mt = 0; mt < 4; mt++)
#pragma unroll
        for (int nt = 0; nt < 4; nt++)
#pragma unroll
            for (int i = 0; i < 4; i++) acc[mt][nt][i] = 0.0f;

    const int nch = K >> 4;

    // prologue: prefetch chunks 0 and 1
#pragma unroll
    for (int c = 0; c < 2; c++) {
        int k0 = c << 4;
        cp_async16(smem_u32(&As[c][lrow][k4]),      Ag + k0);
        cp_async16(smem_u32(&As[c][lrow + 64][k4]), Ag + (size_t)64 * K + k0);
        cp_async16(smem_u32(&Bs[c][lrow][k4]),      Bg + k0);
        cp_async16(smem_u32(&Bs[c][lrow + 64][k4]), Bg + (size_t)64 * K + k0);
        asm volatile("cp.async.commit_group;" ::: "memory");
    }

    int q = lane >> 2, p = lane & 3;

    int buf = 0, nxt = 2;
    for (int c = 0; c < nch; ++c) {
        if (c == nch - 1) asm volatile("cp.async.wait_group 0;" ::: "memory");
        else              asm volatile("cp.async.wait_group 1;" ::: "memory");
        __syncthreads();

        // issue chunk c+2 into buffer (c+2)%3 (its last reader finished chunk c-1)
        if (c + 2 < nch) {
            int k0 = (c + 2) << 4;
            cp_async16(smem_u32(&As[nxt][lrow][k4]),      Ag + k0);
            cp_async16(smem_u32(&As[nxt][lrow + 64][k4]), Ag + (size_t)64 * K + k0);
            cp_async16(smem_u32(&Bs[nxt][lrow][k4]),      Bg + k0);
            cp_async16(smem_u32(&Bs[nxt][lrow + 64][k4]), Bg + (size_t)64 * K + k0);
            asm volatile("cp.async.commit_group;" ::: "memory");
        }

#pragma unroll
        for (int kk = 0; kk < 16; kk += 8) {
            uint32_t afr[4][4], bfr[4][2];
#pragma unroll
            for (int mt = 0; mt < 4; mt++) {
                int r0 = wm * 64 + mt * 16 + q;
                afr[mt][0] = __float_as_uint(As[buf][r0    ][kk + p    ]);
                afr[mt][1] = __float_as_uint(As[buf][r0 + 8][kk + p    ]);
                afr[mt][2] = __float_as_uint(As[buf][r0    ][kk + p + 4]);
                afr[mt][3] = __float_as_uint(As[buf][r0 + 8][kk + p + 4]);
            }
#pragma unroll
            for (int nt = 0; nt < 4; nt++) {
                int n0 = wn * 32 + nt * 8 + q;
                bfr[nt][0] = __float_as_uint(Bs[buf][n0][kk + p    ]);
                bfr[nt][1] = __float_as_uint(Bs[buf][n0][kk + p + 4]);
            }
#pragma unroll
            for (int mt = 0; mt < 4; mt++)
#pragma unroll
                for (int nt = 0; nt < 4; nt++)
                    mma_tf32(acc[mt][nt], afr[mt], bfr[nt]);
        }
        buf = (buf == 2) ? 0 : buf + 1;
        nxt = (nxt == 2) ? 0 : nxt + 1;
    }

    // ---------------- epilogue ----------------
#pragma unroll
    for (int mt = 0; mt < 4; mt++) {
#pragma unroll
        for (int half = 0; half < 2; half++) {
            int r   = bm + wm * 64 + mt * 16 + q + half * 8;
            int dst = (EPI == 2) ? rowmap(r) : r;
            size_t rowbase = (size_t)dst * N;
#pragma unroll
            for (int nt = 0; nt < 4; nt++) {
                int col = bn + wn * 32 + nt * 8 + p * 2;
                float x0 = acc[mt][nt][half * 2 + 0];
                float x1 = acc[mt][nt][half * 2 + 1];
                float2 bi = *(const float2*)(bias + col);
                x0 += bi.x; x1 += bi.y;
                if (EPI == 1) {
                    x0 = tf32r(0.5f * x0 * (1.0f + erff(x0 * 0.70710678118654752f)));
                    x1 = tf32r(0.5f * x1 * (1.0f + erff(x1 * 0.70710678118654752f)));
                } else if (EPI >= 2) {
                    float2 rr = *(const float2*)(res + rowbase + col);
                    x0 += rr.x; x1 += rr.y;
                }
                float2 o; o.x = x0; o.y = x1;
                *(float2*)(Cd + rowbase + col) = o;
            }
        }
    }
}

// ---------------- windowed attention, register-blocked, natural coalesced output ----------------
__global__ void __launch_bounds__(128) attn_kernel(
        const float* __restrict__ qkv,
        const float* __restrict__ bias_table,
        float* __restrict__ out)
{
    int h  = blockIdx.x & 7;
    int bw = blockIdx.x >> 3;
    int widx = bw & 63;

    __shared__ float q[SDIM][36];
    __shared__ float k[SDIM][36];
    __shared__ float v[SDIM][36];
    __shared__ float sc[SDIM][50];
    __shared__ float btab[169];
    __shared__ int   reg[SDIM];

    int tid = threadIdx.x;

    for (int i = tid; i < 169; i += 128) btab[i] = bias_table[i * 8 + h];

    if (tid < SDIM) {
        int sy = tid / 7, sx = tid - sy * 7;
        int sh_h = ((widx >> 3) * 7) + sy;
        int sh_w = ((widx & 7) * 7) + sx;
        int fh = (sh_h < 49) ? 0 : ((sh_h < 53) ? 1 : 2);
        int fw = (sh_w < 49) ? 0 : ((sh_w < 53) ? 1 : 2);
        reg[tid] = (fw == 1) ? 0 : (fh * 3 + fw);
    }

    // load q (scaled), k, v: float4 per unit
    for (int i = tid; i < SDIM * 8; i += 128) {
        int s = i >> 3, d4 = (i & 7) << 2;
        size_t base = (size_t)(bw * 49 + s) * 768 + h * 32 + d4;
        float4 qq = *(const float4*)(qkv + base);
        float4 kk = *(const float4*)(qkv + base + 256);
        float4 vv = *(const float4*)(qkv + base + 512);
        qq.x *= SCALE; qq.y *= SCALE; qq.z *= SCALE; qq.w *= SCALE;
        *(float4*)&q[s][d4] = qq;
        *(float4*)&k[s][d4] = kk;
        *(float4*)&v[s][d4] = vv;
    }
    __syncthreads();

    // score phase: unit = (s, half); q row cached in registers, 4-way split accumulators
    if (tid < 98) {
        int s = tid >> 1, half = tid & 1;
        float4 qr[8];
#pragma unroll
        for (int d4 = 0; d4 < 8; d4++) qr[d4] = *(const float4*)&q[s][d4 << 2];
        int sy = s / 7, sx = s - sy * 7;
        int rs = reg[s];
        int t0 = half * 25, t1 = half ? 49 : 25;
        for (int t = t0; t < t1; t++) {
            float a0 = 0, a1 = 0, a2 = 0, a3 = 0;
#pragma unroll
            for (int d4 = 0; d4 < 8; d4 += 4) {
                float4 k0v = *(const float4*)&k[t][(d4 + 0) << 2];
                float4 k1v = *(const float4*)&k[t][(d4 + 1) << 2];
                float4 k2v = *(const float4*)&k[t][(d4 + 2) << 2];
                float4 k3v = *(const float4*)&k[t][(d4 + 3) << 2];
                a0 += qr[d4+0].x*k0v.x + qr[d4+0].y*k0v.y + qr[d4+0].z*k0v.z + qr[d4+0].w*k0v.w;
                a1 += qr[d4+1].x*k1v.x + qr[d4+1].y*k1v.y + qr[d4+1].z*k1v.z + qr[d4+1].w*k1v.w;
                a2 += qr[d4+2].x*k2v.x + qr[d4+2].y*k2v.y + qr[d4+2].z*k2v.z + qr[d4+2].w*k2v.w;
                a3 += qr[d4+3].x*k3v.x + qr[d4+3].y*k3v.y + qr[d4+3].z*k3v.z + qr[d4+3].w*k3v.w;
            }
            float a = (a0 + a1) + (a2 + a3);
            int ty = t / 7, tx = t - ty * 7;
            a += btab[(sy - ty + 6) * 13 + (sx - tx + 6)];
            if (rs != reg[t]) a -= 100.0f;
            sc[s][t] = a;
        }
    }
    __syncthreads();

    // softmax per row
    if (tid < SDIM) {
        float mx = -1e30f;
#pragma unroll 7
        for (int t = 0; t < 49; t++) mx = fmaxf(mx, sc[tid][t]);
        float sum = 0.0f;
#pragma unroll 7
        for (int t = 0; t < 49; t++) {
            float e = __expf(sc[tid][t] - mx);
            sc[tid][t] = e;
            sum += e;
        }
        float inv = 1.0f / sum;
#pragma unroll 7
        for (int t = 0; t < 49; t++) sc[tid][t] *= inv;
    }
    __syncthreads();

    // AV phase: unit = (s, j): out[s][4j..4j+3], coalesced float4 store
    for (int u = tid; u < SDIM * 8; u += 128) {
        int s = u >> 3, j = u & 7;
        float a0 = 0, a1 = 0, a2 = 0, a3 = 0;
#pragma unroll 7
        for (int t = 0; t < 49; t++) {
            float w = sc[s][t];
            float4 vv = *(const float4*)&v[t][j << 2];
            a0 += w * vv.x; a1 += w * vv.y; a2 += w * vv.z; a3 += w * vv.w;
        }
        float4 o;
        o.x = tf32r(a0); o.y = tf32r(a1); o.z = tf32r(a2); o.w = tf32r(a3);
        *(float4*)(out + (size_t)(bw * 49 + s) * 256 + h * 32 + (j << 2)) = o;
    }
}

// ---------------- launch ----------------
extern "C" void kernel_launch(void* const* d_in, const int* in_sizes, int n_in,
                              void* d_out, int out_size)
{
    const float* x       = (const float*)d_in[0];
    const float* gamma   = (const float*)d_in[1];
    const float* beta    = (const float*)d_in[2];
    const float* qkv_w   = (const float*)d_in[3];
    const float* qkv_b   = (const float*)d_in[4];
    const float* proj_w  = (const float*)d_in[5];
    const float* proj_b  = (const float*)d_in[6];
    const float* relbias = (const float*)d_in[7];
    const float* mlp_w1  = (const float*)d_in[8];
    const float* mlp_b1  = (const float*)d_in[9];
    const float* mlp_w2  = (const float*)d_in[10];
    const float* mlp_b2  = (const float*)d_in[11];
    float* outp = (float*)d_out;

    float *xw, *qkvb, *attnb, *x1, *xn2, *hb, *wT;
    cudaGetSymbolAddress((void**)&xw,    g_xw);
    cudaGetSymbolAddress((void**)&qkvb,  g_qkv);
    cudaGetSymbolAddress((void**)&attnb, g_attn);
    cudaGetSymbolAddress((void**)&x1,    g_x1);
    cudaGetSymbolAddress((void**)&xn2,   g_xn2);
    cudaGetSymbolAddress((void**)&hb,    g_h);
    cudaGetSymbolAddress((void**)&wT,    g_wT);

    const int MT = TOKENS / 128;   // 784

    transpose_k<<<dim3(768/32, 256/32),  dim3(32,8)>>>(qkv_w,  wT + WT_QKV,  256, 768);
    transpose_k<<<dim3(256/32, 256/32),  dim3(32,8)>>>(proj_w, wT + WT_PROJ, 256, 256);
    transpose_k<<<dim3(1024/32, 256/32), dim3(32,8)>>>(mlp_w1, wT + WT_W1,   256, 1024);
    transpose_k<<<dim3(256/32, 1024/32), dim3(32,8)>>>(mlp_w2, wT + WT_W2,   1024, 256);

    ln_kernel<true><<<TOKENS / 8, 256>>>(x, gamma, beta, xw);
    tc_gemm<0><<<dim3(6, MT), 256>>>(xw, wT + WT_QKV, qkv_b, qkvb, nullptr, 768, 256);
    attn_kernel<<<NWINTOT, 128>>>(qkvb, relbias, attnb);
    tc_gemm<2><<<dim3(2, MT), 256>>>(attnb, wT + WT_PROJ, proj_b, x1, x, 256, 256);
    ln_kernel<false><<<TOKENS / 8, 256>>>(x1, gamma, beta, xn2);
    tc_gemm<1><<<dim3(8, MT), 256>>>(xn2, wT + WT_W1, mlp_b1, hb, nullptr, 1024, 256);
    tc_gemm<3><<<dim3(2, MT), 256>>>(hb, wT + WT_W2, mlp_b2, outp, x1, 256, 1024);
}

// round 7
// speedup vs baseline: 1.6049x; 1.0309x over previous
#include <cuda_runtime.h>
#include <math.h>
#include <stdint.h>

// ---------------- static problem config ----------------
#define TOKENS   100352      // 32 * 56 * 56  == 2048 windows * 49
#define CDIM     256
#define SDIM     49
#define IMG      56
#define WIN      7
#define SHIFT    3
#define NMLP     1024
#define NWINTOT  16384
#define SCALE    0.17677669529663687f

// ---------------- device scratch ----------------
__device__ float g_xw  [TOKENS * CDIM];
__device__ float g_qkv [TOKENS * 3 * CDIM];
__device__ float g_attn[TOKENS * CDIM];
__device__ float g_x1  [TOKENS * CDIM];
__device__ float g_xn2 [TOKENS * CDIM];
__device__ float g_h   [TOKENS * NMLP];
__device__ float g_wT  [768*256 + 256*256 + 1024*256 + 256*1024];

#define WT_QKV  0
#define WT_PROJ (768*256)
#define WT_W1   (768*256 + 256*256)
#define WT_W2   (768*256 + 256*256 + 1024*256)

// ---------------- helpers ----------------
__device__ __forceinline__ uint32_t smem_u32(const void* p) {
    uint32_t a;
    asm("{ .reg .u64 t; cvta.to.shared.u64 t, %1; cvt.u32.u64 %0, t; }" : "=r"(a) : "l"(p));
    return a;
}
__device__ __forceinline__ float tf32r(float x) {
    uint32_t u; asm("cvt.rna.tf32.f32 %0, %1;" : "=r"(u) : "f"(x));
    return __uint_as_float(u);
}
__device__ __forceinline__ void cp_async16(uint32_t dst, const void* src) {
    asm volatile("cp.async.cg.shared.global [%0], [%1], 16;" :: "r"(dst), "l"(src));
}
__device__ __forceinline__ void mma_tf32(float* c, const uint32_t* a, const uint32_t* b) {
    asm volatile(
        "mma.sync.aligned.m16n8k8.row.col.f32.tf32.tf32.f32 "
        "{%0,%1,%2,%3}, {%4,%5,%6,%7}, {%8,%9}, {%0,%1,%2,%3};"
        : "+f"(c[0]), "+f"(c[1]), "+f"(c[2]), "+f"(c[3])
        : "r"(a[0]), "r"(a[1]), "r"(a[2]), "r"(a[3]), "r"(b[0]), "r"(b[1]));
}

// window-order row -> token-order row
__device__ __forceinline__ int rowmap(int r) {
    int bw = r / 49;
    int s  = r - bw * 49;
    int b    = bw >> 6;
    int widx = bw & 63;
    int sy = s / 7, sx = s - sy * 7;
    int sh_h = ((widx >> 3) * 7) + sy;
    int sh_w = ((widx & 7) * 7) + sx;
    int oh = sh_h + SHIFT; if (oh >= IMG) oh -= IMG;
    int ow = sh_w + SHIFT; if (ow >= IMG) ow -= IMG;
    return b * (IMG * IMG) + oh * IMG + ow;
}

// ---------------- weight transpose (tf32-rounded): in[K][N] -> out[N][K] ----------------
__global__ void transpose_k(const float* __restrict__ in, float* __restrict__ out,
                            int K, int N)
{
    __shared__ float t[32][33];
    int n0 = blockIdx.x << 5, k0 = blockIdx.y << 5;
    int x = threadIdx.x, y = threadIdx.y;          // 32 x 8
#pragma unroll
    for (int dy = 0; dy < 32; dy += 8)
        t[y + dy][x] = in[(size_t)(k0 + y + dy) * N + n0 + x];
    __syncthreads();
#pragma unroll
    for (int dy = 0; dy < 32; dy += 8)
        out[(size_t)(n0 + y + dy) * K + k0 + x] = tf32r(t[x][y + dy]);
}

// ---------------- LayerNorm (warp per token), tf32-rounded output ----------------
template<bool GATHER>
__global__ void ln_kernel(const float* __restrict__ x,
                          const float* __restrict__ gamma,
                          const float* __restrict__ beta,
                          float* __restrict__ out)
{
    int gw   = (blockIdx.x * blockDim.x + threadIdx.x) >> 5;
    int lane = threadIdx.x & 31;
    if (gw >= TOKENS) return;

    int src = GATHER ? rowmap(gw) : gw;
    const float4* xr = (const float4*)(x + (size_t)src * CDIM);
    float4 v0 = xr[lane];
    float4 v1 = xr[lane + 32];

    float sum = v0.x + v0.y + v0.z + v0.w + v1.x + v1.y + v1.z + v1.w;
    float sq  = v0.x*v0.x + v0.y*v0.y + v0.z*v0.z + v0.w*v0.w
              + v1.x*v1.x + v1.y*v1.y + v1.z*v1.z + v1.w*v1.w;
#pragma unroll
    for (int o = 16; o; o >>= 1) {
        sum += __shfl_xor_sync(0xffffffffu, sum, o);
        sq  += __shfl_xor_sync(0xffffffffu, sq,  o);
    }
    float mu   = sum * (1.0f / 256.0f);
    float var  = sq * (1.0f / 256.0f) - mu * mu;
    float rstd = rsqrtf(var + 1e-5f);

    float4 g0 = ((const float4*)gamma)[lane];
    float4 g1 = ((const float4*)gamma)[lane + 32];
    float4 b0 = ((const float4*)beta )[lane];
    float4 b1 = ((const float4*)beta )[lane + 32];

    float4 o0, o1;
    o0.x = tf32r((v0.x - mu) * rstd * g0.x + b0.x);
    o0.y = tf32r((v0.y - mu) * rstd * g0.y + b0.y);
    o0.z = tf32r((v0.z - mu) * rstd * g0.z + b0.z);
    o0.w = tf32r((v0.w - mu) * rstd * g0.w + b0.w);
    o1.x = tf32r((v1.x - mu) * rstd * g1.x + b1.x);
    o1.y = tf32r((v1.y - mu) * rstd * g1.y + b1.y);
    o1.z = tf32r((v1.z - mu) * rstd * g1.z + b1.z);
    o1.w = tf32r((v1.w - mu) * rstd * g1.w + b1.w);

    float4* orow = (float4*)(out + (size_t)gw * CDIM);
    orow[lane]      = o0;
    orow[lane + 32] = o1;
}

// ---------------- tf32 mma.sync GEMM: C[M,N] = A[M,K] @ Bt[N,K]^T + bias ----------------
// Block 128x128, 4 warps (2m x 2n), warp tile 64x64, k-chunk 16, 3-stage cp.async.
// EPI 0: store   EPI 1: exact GELU + tf32 round   EPI 2: scatter+residual   EPI 3: residual
template<int EPI>
__global__ void __launch_bounds__(128)
tc_gemm(const float* __restrict__ A,
        const float* __restrict__ Bt,
        const float* __restrict__ bias,
        float* __restrict__ Cd,
        const float* __restrict__ res,
        int N, int K)
{
    __shared__ float As[3][128][20];
    __shared__ float Bs[3][128][20];

    int tid  = threadIdx.x;
    int lane = tid & 31;
    int wid  = tid >> 5;
    int wm   = wid >> 1;          // 0..1
    int wn   = wid & 1;           // 0..1
    int bm   = blockIdx.y << 7;
    int bn   = blockIdx.x << 7;

    int arow = tid >> 2;          // 0..31
    int kq   = (tid & 3) << 2;    // 0,4,8,12

    const float* Ag = A  + (size_t)(bm + arow) * K + kq;
    const float* Bg = Bt + (size_t)(bn + arow) * K + kq;

    float acc[4][8][4];
#pragma unroll
    for (int mt = 0; mt < 4; mt++)
#pragma unroll
        for (int nt = 0; nt < 8; nt++)
#pragma unroll
            for (int i = 0; i < 4; i++) acc[mt][nt][i] = 0.0f;

    const int nch = K >> 4;

    // prologue: prefetch chunks 0 and 1
#pragma unroll
    for (int c = 0; c < 2; c++) {
        int k0 = c << 4;
#pragma unroll
        for (int j = 0; j < 4; j++) {
            cp_async16(smem_u32(&As[c][arow + 32*j][kq]), Ag + (size_t)(32*j) * K + k0);
            cp_async16(smem_u32(&Bs[c][arow + 32*j][kq]), Bg + (size_t)(32*j) * K + k0);
        }
        asm volatile("cp.async.commit_group;" ::: "memory");
    }

    int q = lane >> 2, p = lane & 3;

    int buf = 0, nxt = 2;
    for (int c = 0; c < nch; ++c) {
        if (c == nch - 1) asm volatile("cp.async.wait_group 0;" ::: "memory");
        else              asm volatile("cp.async.wait_group 1;" ::: "memory");
        __syncthreads();

        if (c + 2 < nch) {
            int k0 = (c + 2) << 4;
#pragma unroll
            for (int j = 0; j < 4; j++) {
                cp_async16(smem_u32(&As[nxt][arow + 32*j][kq]), Ag + (size_t)(32*j) * K + k0);
                cp_async16(smem_u32(&Bs[nxt][arow + 32*j][kq]), Bg + (size_t)(32*j) * K + k0);
            }
            asm volatile("cp.async.commit_group;" ::: "memory");
        }

#pragma unroll
        for (int kk = 0; kk < 16; kk += 8) {
            uint32_t afr[4][4], bfr[8][2];
#pragma unroll
            for (int mt = 0; mt < 4; mt++) {
                int r0 = wm * 64 + mt * 16 + q;
                afr[mt][0] = __float_as_uint(As[buf][r0    ][kk + p    ]);
                afr[mt][1] = __float_as_uint(As[buf][r0 + 8][kk + p    ]);
                afr[mt][2] = __float_as_uint(As[buf][r0    ][kk + p + 4]);
                afr[mt][3] = __float_as_uint(As[buf][r0 + 8][kk + p + 4]);
            }
#pragma unroll
            for (int nt = 0; nt < 8; nt++) {
                int n0 = wn * 64 + nt * 8 + q;
                bfr[nt][0] = __float_as_uint(Bs[buf][n0][kk + p    ]);
                bfr[nt][1] = __float_as_uint(Bs[buf][n0][kk + p + 4]);
            }
#pragma unroll
            for (int mt = 0; mt < 4; mt++)
#pragma unroll
                for (int nt = 0; nt < 8; nt++)
                    mma_tf32(acc[mt][nt], afr[mt], bfr[nt]);
        }
        buf = (buf == 2) ? 0 : buf + 1;
        nxt = (nxt == 2) ? 0 : nxt + 1;
    }

    // ---------------- epilogue ----------------
#pragma unroll
    for (int mt = 0; mt < 4; mt++) {
#pragma unroll
        for (int half = 0; half < 2; half++) {
            int r   = bm + wm * 64 + mt * 16 + q + half * 8;
            int dst = (EPI == 2) ? rowmap(r) : r;
            size_t rowbase = (size_t)dst * N;
#pragma unroll
            for (int nt = 0; nt < 8; nt++) {
                int col = bn + wn * 64 + nt * 8 + p * 2;
                float x0 = acc[mt][nt][half * 2 + 0];
                float x1 = acc[mt][nt][half * 2 + 1];
                float2 bi = *(const float2*)(bias + col);
                x0 += bi.x; x1 += bi.y;
                if (EPI == 1) {
                    x0 = tf32r(0.5f * x0 * (1.0f + erff(x0 * 0.70710678118654752f)));
                    x1 = tf32r(0.5f * x1 * (1.0f + erff(x1 * 0.70710678118654752f)));
                } else if (EPI >= 2) {
                    float2 rr = *(const float2*)(res + rowbase + col);
                    x0 += rr.x; x1 += rr.y;
                }
                float2 o; o.x = x0; o.y = x1;
                *(float2*)(Cd + rowbase + col) = o;
            }
        }
    }
}

// ---------------- windowed attention via tf32 mma.sync ----------------
// Block = (window, head), 128 threads = 4 warps; warp w owns row tile [16w, 16w+16).
// Scores padded to 64x56; P zeroed outside [49)x[49).
__global__ void __launch_bounds__(128) attn_kernel(
        const float* __restrict__ qkv,
        const float* __restrict__ bias_table,
        float* __restrict__ out)
{
    int h  = blockIdx.x & 7;
    int bw = blockIdx.x >> 3;
    int widx = bw & 63;

    __shared__ float Qs[64][36];
    __shared__ float Ks[56][36];
    __shared__ float Vs[56][36];
    __shared__ float Ps[64][60];   // scores, then softmax probs
    __shared__ float btab[169];
    __shared__ int   reg[SDIM];

    int tid  = threadIdx.x;
    int lane = tid & 31;
    int wrp  = tid >> 5;           // row tile
    int q    = lane >> 2, p = lane & 3;

    for (int i = tid; i < 169; i += 128) btab[i] = bias_table[i * 8 + h];

    if (tid < SDIM) {
        int sy = tid / 7, sx = tid - sy * 7;
        int sh_h = ((widx >> 3) * 7) + sy;
        int sh_w = ((widx & 7) * 7) + sx;
        int fh = (sh_h < 49) ? 0 : ((sh_h < 53) ? 1 : 2);
        int fw = (sh_w < 49) ? 0 : ((sh_w < 53) ? 1 : 2);
        reg[tid] = (fw == 1) ? 0 : (fh * 3 + fw);
    }

    // load q (scaled, tf32), k, v (tf32)
    for (int i = tid; i < SDIM * 8; i += 128) {
        int s = i >> 3, d4 = (i & 7) << 2;
        size_t base = (size_t)(bw * 49 + s) * 768 + h * 32 + d4;
        float4 qq = *(const float4*)(qkv + base);
        float4 kk = *(const float4*)(qkv + base + 256);
        float4 vv = *(const float4*)(qkv + base + 512);
        Qs[s][d4+0] = tf32r(qq.x * SCALE); Qs[s][d4+1] = tf32r(qq.y * SCALE);
        Qs[s][d4+2] = tf32r(qq.z * SCALE); Qs[s][d4+3] = tf32r(qq.w * SCALE);
        Ks[s][d4+0] = tf32r(kk.x); Ks[s][d4+1] = tf32r(kk.y);
        Ks[s][d4+2] = tf32r(kk.z); Ks[s][d4+3] = tf32r(kk.w);
        Vs[s][d4+0] = tf32r(vv.x); Vs[s][d4+1] = tf32r(vv.y);
        Vs[s][d4+2] = tf32r(vv.z); Vs[s][d4+3] = tf32r(vv.w);
    }
    // zero V padding rows 49..55 (guard against NaN garbage in AV mma)
    for (int i = tid; i < 7 * 32; i += 128)
        Vs[49 + (i >> 5)][i & 31] = 0.0f;
    __syncthreads();

    // ----- scores: S = Q @ K^T via mma (rows 16w..16w+15, cols 0..55) -----
    {
        int r0 = wrp * 16 + q;
        uint32_t afr[4][4];
#pragma unroll
        for (int kd = 0; kd < 4; kd++) {
            afr[kd][0] = __float_as_uint(Qs[r0    ][kd*8 + p    ]);
            afr[kd][1] = __float_as_uint(Qs[r0 + 8][kd*8 + p    ]);
            afr[kd][2] = __float_as_uint(Qs[r0    ][kd*8 + p + 4]);
            afr[kd][3] = __float_as_uint(Qs[r0 + 8][kd*8 + p + 4]);
        }
#pragma unroll
        for (int ct = 0; ct < 7; ct++) {
            float accS[4] = {0, 0, 0, 0};
#pragma unroll
            for (int kd = 0; kd < 4; kd++) {
                uint32_t bfr[2];
                bfr[0] = __float_as_uint(Ks[ct*8 + q][kd*8 + p    ]);
                bfr[1] = __float_as_uint(Ks[ct*8 + q][kd*8 + p + 4]);
                mma_tf32(accS, afr[kd], bfr);
            }
            *(float2*)&Ps[r0    ][ct*8 + 2*p] = make_float2(accS[0], accS[1]);
            *(float2*)&Ps[r0 + 8][ct*8 + 2*p] = make_float2(accS[2], accS[3]);
        }
    }
    __syncthreads();

    // ----- softmax (rows) + padding zeros -----
    if (tid < SDIM) {
        int s = tid;
        int sy = s / 7, sx = s - sy * 7;
        int rs = reg[s];
        float mx = -1e30f;
#pragma unroll 7
        for (int t = 0; t < 49; t++) {
            int ty = t / 7, tx = t - ty * 7;
            float a = Ps[s][t] + btab[(sy - ty + 6) * 13 + (sx - tx + 6)];
            if (rs != reg[t]) a -= 100.0f;
            Ps[s][t] = a;
            mx = fmaxf(mx, a);
        }
        float sum = 0.0f;
#pragma unroll 7
        for (int t = 0; t < 49; t++) {
            float e = __expf(Ps[s][t] - mx);
            Ps[s][t] = e;
            sum += e;
        }
        float inv = 1.0f / sum;
#pragma unroll 7
        for (int t = 0; t < 49; t++) Ps[s][t] *= inv;
#pragma unroll
        for (int t = 49; t < 56; t++) Ps[s][t] = 0.0f;
    } else {
        // zero P rows 49..63 (cols 0..55)
        for (int i = tid - 49; i < 15 * 56; i += 79) {
            int rr = 49 + i / 56, cc = i % 56;
            Ps[rr][cc] = 0.0f;
        }
    }
    __syncthreads();

    // ----- AV: O = P @ V via mma (k = t, 7 steps) -----
    {
        int r0 = wrp * 16 + q;
        float accO[4][4];
#pragma unroll
        for (int ct = 0; ct < 4; ct++)
#pragma unroll
            for (int i = 0; i < 4; i++) accO[ct][i] = 0.0f;

#pragma unroll
        for (int kt = 0; kt < 7; kt++) {
            uint32_t afr[4];
            afr[0] = __float_as_uint(Ps[r0    ][kt*8 + p    ]);
            afr[1] = __float_as_uint(Ps[r0 + 8][kt*8 + p    ]);
            afr[2] = __float_as_uint(Ps[r0    ][kt*8 + p + 4]);
            afr[3] = __float_as_uint(Ps[r0 + 8][kt*8 + p + 4]);
#pragma unroll
            for (int ct = 0; ct < 4; ct++) {
                uint32_t bfr[2];
                bfr[0] = __float_as_uint(Vs[kt*8 + p    ][ct*8 + q]);
                bfr[1] = __float_as_uint(Vs[kt*8 + p + 4][ct*8 + q]);
                mma_tf32(accO[ct], afr, bfr);
            }
        }

        int s0 = r0, s1 = r0 + 8;
#pragma unroll
        for (int ct = 0; ct < 4; ct++) {
            int col = h * 32 + ct * 8 + 2 * p;
            if (s0 < SDIM) {
                float2 o; o.x = tf32r(accO[ct][0]); o.y = tf32r(accO[ct][1]);
                *(float2*)(out + (size_t)(bw * 49 + s0) * 256 + col) = o;
            }
            if (s1 < SDIM) {
                float2 o; o.x = tf32r(accO[ct][2]); o.y = tf32r(accO[ct][3]);
                *(float2*)(out + (size_t)(bw * 49 + s1) * 256 + col) = o;
            }
        }
    }
}

// ---------------- launch ----------------
extern "C" void kernel_launch(void* const* d_in, const int* in_sizes, int n_in,
                              void* d_out, int out_size)
{
    const float* x       = (const float*)d_in[0];
    const float* gamma   = (const float*)d_in[1];
    const float* beta    = (const float*)d_in[2];
    const float* qkv_w   = (const float*)d_in[3];
    const float* qkv_b   = (const float*)d_in[4];
    const float* proj_w  = (const float*)d_in[5];
    const float* proj_b  = (const float*)d_in[6];
    const float* relbias = (const float*)d_in[7];
    const float* mlp_w1  = (const float*)d_in[8];
    const float* mlp_b1  = (const float*)d_in[9];
    const float* mlp_w2  = (const float*)d_in[10];
    const float* mlp_b2  = (const float*)d_in[11];
    float* outp = (float*)d_out;

    float *xw, *qkvb, *attnb, *x1, *xn2, *hb, *wT;
    cudaGetSymbolAddress((void**)&xw,    g_xw);
    cudaGetSymbolAddress((void**)&qkvb,  g_qkv);
    cudaGetSymbolAddress((void**)&attnb, g_attn);
    cudaGetSymbolAddress((void**)&x1,    g_x1);
    cudaGetSymbolAddress((void**)&xn2,   g_xn2);
    cudaGetSymbolAddress((void**)&hb,    g_h);
    cudaGetSymbolAddress((void**)&wT,    g_wT);

    const int MT = TOKENS / 128;   // 784

    transpose_k<<<dim3(768/32, 256/32),  dim3(32,8)>>>(qkv_w,  wT + WT_QKV,  256, 768);
    transpose_k<<<dim3(256/32, 256/32),  dim3(32,8)>>>(proj_w, wT + WT_PROJ, 256, 256);
    transpose_k<<<dim3(1024/32, 256/32), dim3(32,8)>>>(mlp_w1, wT + WT_W1,   256, 1024);
    transpose_k<<<dim3(256/32, 1024/32), dim3(32,8)>>>(mlp_w2, wT + WT_W2,   1024, 256);

    ln_kernel<true><<<TOKENS / 8, 256>>>(x, gamma, beta, xw);
    tc_gemm<0><<<dim3(6, MT), 128>>>(xw, wT + WT_QKV, qkv_b, qkvb, nullptr, 768, 256);
    attn_kernel<<<NWINTOT, 128>>>(qkvb, relbias, attnb);
    tc_gemm<2><<<dim3(2, MT), 128>>>(attnb, wT + WT_PROJ, proj_b, x1, x, 256, 256);
    ln_kernel<false><<<TOKENS / 8, 256>>>(x1, gamma, beta, xn2);
    tc_gemm<1><<<dim3(8, MT), 128>>>(xn2, wT + WT_W1, mlp_b1, hb, nullptr, 1024, 256);
    tc_gemm<3><<<dim3(2, MT), 128>>>(hb, wT + WT_W2, mlp_b2, outp, x1, 256, 1024);
}